// round 10
// baseline (speedup 1.0000x reference)
#include <cuda_runtime.h>
#include <cstdint>

// ---------------- constants ----------------
#define T_FRAMES 2049
#define NWAV     262144
#define MW       16699
#define LEFT     24418
#define PADR     32768
#define NB       96
#define NC       20
#define NF       576            // 192 bins x 3 sub-frequencies
#define ECOLS    2304           // [full 1152 | partial 1152]
#define GROWS    2368
#define XW_LEN   294912         // 2304*128
#define TPAD     2176

// stage-2 tiling: 18 complex freqs (=3 cqt bins worth of lo/hi) x 112 frames
#define FTILE2   18
#define TTILE2   112
#define TT2      19             // 19*112 = 2128 >= 2049
#define FB2      32             // 576/18
#define GS_STR   247            // float2 stride, rows 0..244
#define HS_STR   233            // float2 stride, rows 0..231
#define GP_STR   113            // rows 0..111
#define ZS_STR   113
#define W2ROWS   24             // 13 H-taps + 10 Z-taps + 1 partial

// setup kernel block ranges
#define PAD_BLKS 1152           // 294912/256
#define E_BLKS   288
#define W_ELEMS  (NF * W2ROWS)  // 13824
#define W_BLKS   54
#define SETUP_BLKS (PAD_BLKS + E_BLKS + W_BLKS + 1)

// ---------------- device scratch ----------------
__device__ float g_xw[XW_LEN];
__device__ float g_e[128 * ECOLS];
__device__ float g_w2[W2ROWS * 1152];
__device__ float g_g[(size_t)GROWS * ECOLS];
__device__ float g_lpT[(size_t)NB * TPAD];      // log cqt power, [bin][t]
__device__ float g_alpha[NB];
__device__ float g_dct[NC * NB];

// ---------------- f32x2 helpers ----------------
__device__ __forceinline__ void fma2(unsigned long long& acc,
                                     unsigned long long a, unsigned long long b) {
    asm("fma.rn.f32x2 %0, %1, %2, %0;" : "+l"(acc) : "l"(a), "l"(b));
}
__device__ __forceinline__ unsigned long long dup2(float x) {
    unsigned long long r;
    asm("mov.b64 %0, {%1, %1};" : "=l"(r) : "f"(x));
    return r;
}
__device__ __forceinline__ unsigned long long pk2(float x, float y) {
    unsigned long long r;
    asm("mov.b64 %0, {%1, %2};" : "=l"(r) : "f"(x), "f"(y));
    return r;
}
__device__ __forceinline__ float2 upk2(unsigned long long v) {
    float2 r;
    asm("mov.b64 {%0, %1}, %2;" : "=f"(r.x), "=f"(r.y) : "l"(v));
    return r;
}

// ---------------- inline bin computation ----------------
__device__ __forceinline__ int bin_of(int bi) {   // bi 0..191
    int i = bi >> 1;
    float cq   = 32.7f * exp2f((float)i / 24.0f);
    float idxf = cq / 8000.0f * 32768.0f;
    int lo = (int)idxf;
    lo = max(0, min(lo, 32767));
    return lo + (bi & 1);
}

// ---------------- fused setup ----------------
__global__ void __launch_bounds__(256) k_setup(const float* __restrict__ wav) {
    const int blk = blockIdx.x;
    const int tid = threadIdx.x;

    if (blk < PAD_BLKS) {
        int i = blk * 256 + tid;
        int q = i + (LEFT - PADR);
        int idx = (q < 0) ? -q : ((q >= NWAV) ? (2 * NWAV - 2 - q) : q);
        idx = max(0, min(idx, NWAV - 1));
        g_xw[i] = wav[idx];
        return;
    }
    if (blk < PAD_BLKS + E_BLKS) {
        int fi = (blk - PAD_BLKS) * 2 + (tid >> 7);
        int r  = tid & 127;
        int bi = fi / 3, j = fi % 3;
        int b  = bin_of(bi);
        float fb = (float)((b * r) & 65535) * (1.0f / 65536.0f);
        float fs = (float)r * (1.0f / (float)MW);
        float fr = fb + ((j == 1) ? -fs : (j == 2) ? fs : 0.0f);
        float s, c;
        sincospif(2.0f * fr, &s, &c);
        float re = c, im = -s;
        g_e[r * ECOLS + 2 * fi]     = re;
        g_e[r * ECOLS + 2 * fi + 1] = im;
        float rp = (r < 59) ? re : 0.0f;
        float ip = (r < 59) ? im : 0.0f;
        g_e[r * ECOLS + 1152 + 2 * fi]     = rp;
        g_e[r * ECOLS + 1152 + 2 * fi + 1] = ip;
        return;
    }
    if (blk < PAD_BLKS + E_BLKS + W_BLKS) {
        int lin = (blk - PAD_BLKS - E_BLKS) * 256 + tid;
        if (lin >= W_ELEMS) return;
        int fi = lin / W2ROWS;
        int u  = lin % W2ROWS;
        int bi = fi / 3, j = fi % 3;
        int b  = bin_of(bi);
        int sgn = (j == 1) ? -1 : (j == 2) ? 1 : 0;
        float wre, wim;
        if (u < 13) {
            float fa = (float)((b * u) & 511) * (1.0f / 512.0f);
            float fbv = (float)(128 * u) * (1.0f / (float)MW);
            float fr = fa + (float)sgn * fbv;
            float s, c;
            sincospif(2.0f * fr, &s, &c);
            wre = c; wim = -s;
        } else {
            float coeff = (j == 0) ? 0.5f : -0.25f;
            int e = (u < 23) ? 13 * (u - 13) : 130;
            float fa = (float)((b * e) & 511) * (1.0f / 512.0f);
            float fbv = (float)((128 * e) % MW) * (1.0f / (float)MW);
            float fr = fa + (float)sgn * fbv;
            float s, c;
            sincospif(2.0f * fr, &s, &c);
            wre = coeff * c;
            wim = -coeff * s;
        }
        g_w2[u * 1152 + 2 * fi]     = wre;
        g_w2[u * 1152 + 2 * fi + 1] = wim;
        return;
    }
    // last block: alpha + dct
    if (tid < NB) {
        float cq   = 32.7f * exp2f((float)tid / 24.0f);
        float idxf = cq / 8000.0f * 32768.0f;
        int lo = (int)idxf;
        lo = max(0, min(lo, 32767));
        g_alpha[tid] = idxf - (float)lo;
    }
    for (int idx = tid; idx < NC * NB; idx += 256) {
        int c = idx / NB, n = idx % NB;
        g_dct[idx] = cospif((float)(c * (2 * n + 1)) / 192.0f);
    }
}

// ---------------- stage 1: G[s, col] = sum_r xw[128s + r] * E[r, col] ----------------
__global__ void __launch_bounds__(256) k_s1() {
    extern __shared__ float smem[];
    float* xs = smem;            // 16384 floats
    float* ts = smem + 16384;    // up to 128 x 64

    const int bx = blockIdx.x;                 // 0..35
    const int c0 = bx * 64;
    const int K  = (bx < 18) ? 128 : 64;
    const int s0 = blockIdx.y * 128;
    const int tid = threadIdx.x;
    const int cg = tid & 15;
    const int fg = tid >> 4;

    const float4* xsrc = (const float4*)(g_xw + s0 * 128);
    #pragma unroll
    for (int i = tid; i < 4096; i += 256)
        ((float4*)xs)[i] = xsrc[i];
    for (int i = tid; i < K * 16; i += 256) {
        int kk = i >> 4, c4 = i & 15;
        ((float4*)ts)[i] = *(const float4*)(g_e + kk * ECOLS + c0 + c4 * 4);
    }
    __syncthreads();

    unsigned long long acc[8][2] = {};
    for (int kk0 = 0; kk0 < K; kk0 += 4) {
        float4 af[8];
        #pragma unroll
        for (int r = 0; r < 8; r++)
            af[r] = *(const float4*)(xs + (fg * 8 + r) * 128 + kk0);
        #pragma unroll
        for (int k = 0; k < 4; k++) {
            ulonglong2 bb = *(const ulonglong2*)(ts + (kk0 + k) * 64 + cg * 4);
            #pragma unroll
            for (int r = 0; r < 8; r++) {
                unsigned long long ad = dup2(((const float*)&af[r])[k]);
                fma2(acc[r][0], ad, bb.x);
                fma2(acc[r][1], ad, bb.y);
            }
        }
    }

    #pragma unroll
    for (int r = 0; r < 8; r++) {
        int s = s0 + fg * 8 + r;
        ulonglong2 v;
        v.x = acc[r][0]; v.y = acc[r][1];
        *(ulonglong2*)(g_g + (size_t)s * ECOLS + c0 + cg * 4) = v;
    }
}

// ---------------- stage 2: two-level FIR (13 x 10) + partial + fused power/log ----------------
__global__ void __launch_bounds__(256) k_s2() {
    extern __shared__ float smem[];
    float2* Gs = (float2*)smem;               // [18][GS_STR], rows 0..244
    float2* Hs = Gs + FTILE2 * GS_STR;        // [18][HS_STR], rows 0..231
    float2* Gp = Hs + FTILE2 * HS_STR;        // [18][GP_STR], rows 0..111
    float2* Wt = Gp + FTILE2 * GP_STR;        // [24][18]

    const int m   = blockIdx.x;               // bin-triple 0..31
    const int fc0 = m * FTILE2;
    const int t0  = blockIdx.y * TTILE2;
    const int tid = threadIdx.x;

    for (int idx = tid; idx < 245 * 9; idx += 256) {
        int row = idx / 9, p = idx % 9;
        float4 v = *(const float4*)(g_g + (size_t)(t0 + row) * ECOLS + fc0 * 2 + p * 4);
        Gs[(2 * p) * GS_STR + row]     = make_float2(v.x, v.y);
        Gs[(2 * p + 1) * GS_STR + row] = make_float2(v.z, v.w);
    }
    for (int idx = tid; idx < 112 * 9; idx += 256) {
        int row = idx / 9, p = idx % 9;
        float4 v = *(const float4*)(g_g + (size_t)(t0 + 130 + row) * ECOLS + 1152 + fc0 * 2 + p * 4);
        Gp[(2 * p) * GP_STR + row]     = make_float2(v.x, v.y);
        Gp[(2 * p + 1) * GP_STR + row] = make_float2(v.z, v.w);
    }
    for (int idx = tid; idx < W2ROWS * 9; idx += 256) {
        int u = idx / 9, p = idx % 9;
        float4 v = *(const float4*)(g_w2 + u * 1152 + fc0 * 2 + p * 4);
        Wt[u * FTILE2 + 2 * p]     = make_float2(v.x, v.y);
        Wt[u * FTILE2 + 2 * p + 1] = make_float2(v.z, v.w);
    }
    __syncthreads();

    // ---- H phase: H[tau,f] = sum_{w<13} rho^w G[tau+w,f], rows 0..231 ----
    for (int cid = tid; cid < 522; cid += 256) {     // 18 f x 29 chunks of 8 rows
        int f = cid % 18, ch = cid / 18;
        int base = ch * 8;
        const float2* gb = Gs + f * GS_STR + base;
        unsigned long long gw[8], gsw[8], acc[8];
        #pragma unroll
        for (int r = 0; r < 8; r++) acc[r] = 0ULL;
        #pragma unroll
        for (int i = 0; i < 7; i++) {
            float2 g = gb[i];
            gw[i]  = pk2(g.x, g.y);
            gsw[i] = pk2(-g.y, g.x);
        }
        #pragma unroll
        for (int u = 0; u < 13; u++) {
            float2 g = gb[u + 7];
            gw[(u + 7) & 7]  = pk2(g.x, g.y);
            gsw[(u + 7) & 7] = pk2(-g.y, g.x);
            float2 wt = Wt[u * FTILE2 + f];
            unsigned long long wx = dup2(wt.x);
            unsigned long long wy = dup2(wt.y);
            #pragma unroll
            for (int r = 0; r < 8; r++) {
                fma2(acc[r], wx, gw[(u + r) & 7]);
                fma2(acc[r], wy, gsw[(u + r) & 7]);
            }
        }
        float2* hb = Hs + f * HS_STR + base;
        #pragma unroll
        for (int r = 0; r < 8; r++) hb[r] = upk2(acc[r]);
    }
    __syncthreads();

    // ---- Z phase ----
    const int f  = tid % 18;
    const int tg = tid / 18;
    const bool active = (tid < 252);
    const int base = tg * 8;
    unsigned long long acc[8] = {};
    if (active) {
        const float2* hb = Hs + f * HS_STR + base;
        #pragma unroll
        for (int v = 0; v < 10; v++) {
            float2 wt = Wt[(13 + v) * FTILE2 + f];
            unsigned long long wx = dup2(wt.x);
            unsigned long long wy = dup2(wt.y);
            #pragma unroll
            for (int r = 0; r < 8; r++) {
                float2 h = hb[13 * v + r];
                fma2(acc[r], wx, pk2(h.x, h.y));
                fma2(acc[r], wy, pk2(-h.y, h.x));
            }
        }
        float2 wt = Wt[23 * FTILE2 + f];
        unsigned long long wx = dup2(wt.x);
        unsigned long long wy = dup2(wt.y);
        const float2* gp = Gp + f * GP_STR + base;
        #pragma unroll
        for (int r = 0; r < 8; r++) {
            float2 g = gp[r];
            fma2(acc[r], wx, pk2(g.x, g.y));
            fma2(acc[r], wy, pk2(-g.y, g.x));
        }
    }
    __syncthreads();
    float2* Zs = Gs;
    if (active) {
        #pragma unroll
        for (int r = 0; r < 8; r++)
            Zs[f * ZS_STR + base + r] = upk2(acc[r]);
    }
    __syncthreads();

    // ---- combine triples -> power -> lerp -> log ----
    for (int idx = tid; idx < 3 * TTILE2; idx += 256) {
        int q  = idx / TTILE2;
        int tl = idx % TTILE2;
        int t  = t0 + tl;
        if (t >= T_FRAMES) continue;
        const float2* zq = Zs + (6 * q) * ZS_STR + tl;
        float2 z0 = zq[0];
        float2 z1 = zq[ZS_STR];
        float2 z2 = zq[2 * ZS_STR];
        float2 z3 = zq[3 * ZS_STR];
        float2 z4 = zq[4 * ZS_STR];
        float2 z5 = zq[5 * ZS_STR];
        float lre = z0.x + z1.x + z2.x, lim = z0.y + z1.y + z2.y;
        float hre = z3.x + z4.x + z5.x, him = z3.y + z4.y + z5.y;
        float plo = lre * lre + lim * lim;
        float phi = hre * hre + him * him;
        int bin = 3 * m + q;
        float al = g_alpha[bin];
        float p = (1.0f - al) * plo + al * phi;
        g_lpT[(size_t)bin * TPAD + t] = logf(fmaxf(p, 1e-8f));
    }
}

// ---------------- fused DCT + normalize + delta + delta-delta ----------------
// block c (20 blocks): computes its own cepstral column from g_lpT, then stats.
__global__ void __launch_bounds__(256) k_tail(float* __restrict__ out) {
    const int c = blockIdx.x;       // 0..19
    const int tid = threadIdx.x;
    __shared__ float dctc[NB];
    __shared__ float cn[2050];
    __shared__ float d1s[T_FRAMES];
    __shared__ float red[256];

    if (tid < NB) dctc[tid] = g_dct[c * NB + tid];
    __syncthreads();

    // DCT: cn[t] = sum_n lpT[n][t] * dctc[n], two frames at a time via FMA2
    float s = 0.0f;
    for (int p = tid; p < 1025; p += 256) {
        int t = 2 * p;
        unsigned long long acc = 0ULL;
        #pragma unroll 8
        for (int n = 0; n < NB; n++) {
            unsigned long long gv = *(const unsigned long long*)(g_lpT + (size_t)n * TPAD + t);
            fma2(acc, dup2(dctc[n]), gv);
        }
        float2 r = upk2(acc);
        cn[t] = r.x;
        cn[t + 1] = r.y;                       // t=2049 lands in padding slot
        s += r.x + ((t + 1 < T_FRAMES) ? r.y : 0.0f);
    }
    red[tid] = s; __syncthreads();
    for (int o = 128; o; o >>= 1) { if (tid < o) red[tid] += red[tid + o]; __syncthreads(); }
    float mean = red[0] / (float)T_FRAMES;
    __syncthreads();
    float ss = 0.0f;
    for (int t = tid; t < T_FRAMES; t += 256) { float d = cn[t] - mean; ss += d * d; }
    red[tid] = ss; __syncthreads();
    for (int o = 128; o; o >>= 1) { if (tid < o) red[tid] += red[tid + o]; __syncthreads(); }
    float inv = 1.0f / (sqrtf(red[0] / (float)(T_FRAMES - 1)) + 1e-8f);
    __syncthreads();
    for (int t = tid; t < T_FRAMES; t += 256) cn[t] = (cn[t] - mean) * inv;
    __syncthreads();

    for (int t = tid; t < T_FRAMES; t += 256) {
        int tp1 = min(t + 1, T_FRAMES - 1), tm1 = max(t - 1, 0);
        int tp2 = min(t + 2, T_FRAMES - 1), tm2 = max(t - 2, 0);
        float d = ((cn[tp1] - cn[tm1]) + 2.0f * (cn[tp2] - cn[tm2])) * 0.1f;
        d1s[t] = d;
        out[t * 60 + c]      = cn[t];
        out[t * 60 + 20 + c] = d;
    }
    __syncthreads();
    for (int t = tid; t < T_FRAMES; t += 256) {
        int tp1 = min(t + 1, T_FRAMES - 1), tm1 = max(t - 1, 0);
        int tp2 = min(t + 2, T_FRAMES - 1), tm2 = max(t - 2, 0);
        float d = ((d1s[tp1] - d1s[tm1]) + 2.0f * (d1s[tp2] - d1s[tm2])) * 0.1f;
        out[t * 60 + 40 + c] = d;
    }
}

// ---------------- launch ----------------
extern "C" void kernel_launch(void* const* d_in, const int* in_sizes, int n_in,
                              void* d_out, int out_size) {
    const float* wav = (const float*)d_in[0];
    float* out = (float*)d_out;

    const int s1_smem = (16384 + 128 * 64) * 4;   // 98304
    const int s2_smem = (FTILE2 * GS_STR + FTILE2 * HS_STR + FTILE2 * GP_STR
                         + W2ROWS * FTILE2) * 8;  // 88848
    cudaFuncSetAttribute(k_s1, cudaFuncAttributeMaxDynamicSharedMemorySize, s1_smem);
    cudaFuncSetAttribute(k_s2, cudaFuncAttributeMaxDynamicSharedMemorySize, s2_smem);

    k_setup<<<SETUP_BLKS, 256>>>(wav);
    k_s1<<<dim3(36, 18), 256, s1_smem>>>();
    k_s2<<<dim3(FB2, TT2), 256, s2_smem>>>();
    k_tail<<<NC, 256>>>(out);
}

// round 11
// speedup vs baseline: 1.2132x; 1.2132x over previous
#include <cuda_runtime.h>
#include <cstdint>

// ---------------- constants ----------------
#define T_FRAMES 2049
#define NWAV     262144
#define MW       16699
#define LEFT     24418
#define PADR     32768
#define NB       96
#define NC       20
#define NF       576            // 192 bins x 3 sub-frequencies
#define ECOLS    2304           // [full 1152 | partial 1152]
#define GROWS    2368
#define XW_LEN   294912         // 2304*128
#define TPAD     2176

// stage-2 tiling
#define FTILE2   18
#define TTILE2   112
#define TT2      19
#define FB2      32
#define GS_STR   247
#define HS_STR   233
#define GP_STR   113
#define ZS_STR   113
#define W2ROWS   24

// setup kernel block ranges
#define PAD_BLKS 1152
#define E_BLKS   288
#define W_ELEMS  (NF * W2ROWS)
#define W_BLKS   54
#define SETUP_BLKS (PAD_BLKS + E_BLKS + W_BLKS + 1)

// ---------------- device scratch ----------------
__device__ float g_xw[XW_LEN];
__device__ float g_e[128 * ECOLS];
__device__ float g_w2[W2ROWS * 1152];
__device__ float g_g[(size_t)GROWS * ECOLS];
__device__ float g_lpT[(size_t)NB * TPAD];      // log cqt power, [bin][t]
__device__ float g_c[T_FRAMES * NC];
__device__ float g_alpha[NB];
__device__ float g_dct[NC * NB];

// ---------------- f32x2 helpers ----------------
__device__ __forceinline__ void fma2(unsigned long long& acc,
                                     unsigned long long a, unsigned long long b) {
    asm("fma.rn.f32x2 %0, %1, %2, %0;" : "+l"(acc) : "l"(a), "l"(b));
}
__device__ __forceinline__ unsigned long long dup2(float x) {
    unsigned long long r;
    asm("mov.b64 %0, {%1, %1};" : "=l"(r) : "f"(x));
    return r;
}
__device__ __forceinline__ unsigned long long pk2(float x, float y) {
    unsigned long long r;
    asm("mov.b64 %0, {%1, %2};" : "=l"(r) : "f"(x), "f"(y));
    return r;
}
__device__ __forceinline__ float2 upk2(unsigned long long v) {
    float2 r;
    asm("mov.b64 {%0, %1}, %2;" : "=f"(r.x), "=f"(r.y) : "l"(v));
    return r;
}

// ---------------- inline bin computation ----------------
__device__ __forceinline__ int bin_of(int bi) {   // bi 0..191
    int i = bi >> 1;
    float cq   = 32.7f * exp2f((float)i / 24.0f);
    float idxf = cq / 8000.0f * 32768.0f;
    int lo = (int)idxf;
    lo = max(0, min(lo, 32767));
    return lo + (bi & 1);
}

// ---------------- fused setup ----------------
__global__ void __launch_bounds__(256) k_setup(const float* __restrict__ wav) {
    const int blk = blockIdx.x;
    const int tid = threadIdx.x;

    if (blk < PAD_BLKS) {
        int i = blk * 256 + tid;
        int q = i + (LEFT - PADR);
        int idx = (q < 0) ? -q : ((q >= NWAV) ? (2 * NWAV - 2 - q) : q);
        idx = max(0, min(idx, NWAV - 1));
        g_xw[i] = wav[idx];
        return;
    }
    if (blk < PAD_BLKS + E_BLKS) {
        int fi = (blk - PAD_BLKS) * 2 + (tid >> 7);
        int r  = tid & 127;
        int bi = fi / 3, j = fi % 3;
        int b  = bin_of(bi);
        float fb = (float)((b * r) & 65535) * (1.0f / 65536.0f);
        float fs = (float)r * (1.0f / (float)MW);
        float fr = fb + ((j == 1) ? -fs : (j == 2) ? fs : 0.0f);
        float s, c;
        sincospif(2.0f * fr, &s, &c);
        float re = c, im = -s;
        g_e[r * ECOLS + 2 * fi]     = re;
        g_e[r * ECOLS + 2 * fi + 1] = im;
        float rp = (r < 59) ? re : 0.0f;
        float ip = (r < 59) ? im : 0.0f;
        g_e[r * ECOLS + 1152 + 2 * fi]     = rp;
        g_e[r * ECOLS + 1152 + 2 * fi + 1] = ip;
        return;
    }
    if (blk < PAD_BLKS + E_BLKS + W_BLKS) {
        int lin = (blk - PAD_BLKS - E_BLKS) * 256 + tid;
        if (lin >= W_ELEMS) return;
        int fi = lin / W2ROWS;
        int u  = lin % W2ROWS;
        int bi = fi / 3, j = fi % 3;
        int b  = bin_of(bi);
        int sgn = (j == 1) ? -1 : (j == 2) ? 1 : 0;
        float wre, wim;
        if (u < 13) {
            float fa = (float)((b * u) & 511) * (1.0f / 512.0f);
            float fbv = (float)(128 * u) * (1.0f / (float)MW);
            float fr = fa + (float)sgn * fbv;
            float s, c;
            sincospif(2.0f * fr, &s, &c);
            wre = c; wim = -s;
        } else {
            float coeff = (j == 0) ? 0.5f : -0.25f;
            int e = (u < 23) ? 13 * (u - 13) : 130;
            float fa = (float)((b * e) & 511) * (1.0f / 512.0f);
            float fbv = (float)((128 * e) % MW) * (1.0f / (float)MW);
            float fr = fa + (float)sgn * fbv;
            float s, c;
            sincospif(2.0f * fr, &s, &c);
            wre = coeff * c;
            wim = -coeff * s;
        }
        g_w2[u * 1152 + 2 * fi]     = wre;
        g_w2[u * 1152 + 2 * fi + 1] = wim;
        return;
    }
    // last block: alpha + dct
    if (tid < NB) {
        float cq   = 32.7f * exp2f((float)tid / 24.0f);
        float idxf = cq / 8000.0f * 32768.0f;
        int lo = (int)idxf;
        lo = max(0, min(lo, 32767));
        g_alpha[tid] = idxf - (float)lo;
    }
    for (int idx = tid; idx < NC * NB; idx += 256) {
        int c = idx / NB, n = idx % NB;
        g_dct[idx] = cospif((float)(c * (2 * n + 1)) / 192.0f);
    }
}

// ---------------- stage 1: G[s, col] = sum_r xw[128s + r] * E[r, col] ----------------
__global__ void __launch_bounds__(256) k_s1() {
    extern __shared__ float smem[];
    float* xs = smem;            // 16384 floats
    float* ts = smem + 16384;    // up to 128 x 64

    const int bx = blockIdx.x;                 // 0..35
    const int c0 = bx * 64;
    const int K  = (bx < 18) ? 128 : 64;
    const int s0 = blockIdx.y * 128;
    const int tid = threadIdx.x;
    const int cg = tid & 15;
    const int fg = tid >> 4;

    const float4* xsrc = (const float4*)(g_xw + s0 * 128);
    #pragma unroll
    for (int i = tid; i < 4096; i += 256)
        ((float4*)xs)[i] = xsrc[i];
    for (int i = tid; i < K * 16; i += 256) {
        int kk = i >> 4, c4 = i & 15;
        ((float4*)ts)[i] = *(const float4*)(g_e + kk * ECOLS + c0 + c4 * 4);
    }
    __syncthreads();

    unsigned long long acc[8][2] = {};
    for (int kk0 = 0; kk0 < K; kk0 += 4) {
        float4 af[8];
        #pragma unroll
        for (int r = 0; r < 8; r++)
            af[r] = *(const float4*)(xs + (fg * 8 + r) * 128 + kk0);
        #pragma unroll
        for (int k = 0; k < 4; k++) {
            ulonglong2 bb = *(const ulonglong2*)(ts + (kk0 + k) * 64 + cg * 4);
            #pragma unroll
            for (int r = 0; r < 8; r++) {
                unsigned long long ad = dup2(((const float*)&af[r])[k]);
                fma2(acc[r][0], ad, bb.x);
                fma2(acc[r][1], ad, bb.y);
            }
        }
    }

    #pragma unroll
    for (int r = 0; r < 8; r++) {
        int s = s0 + fg * 8 + r;
        ulonglong2 v;
        v.x = acc[r][0]; v.y = acc[r][1];
        *(ulonglong2*)(g_g + (size_t)s * ECOLS + c0 + cg * 4) = v;
    }
}

// ---------------- stage 2: two-level FIR (13 x 10) + partial + fused power/log ----------------
__global__ void __launch_bounds__(256) k_s2() {
    extern __shared__ float smem[];
    float2* Gs = (float2*)smem;               // [18][GS_STR], rows 0..244
    float2* Hs = Gs + FTILE2 * GS_STR;        // [18][HS_STR], rows 0..231
    float2* Gp = Hs + FTILE2 * HS_STR;        // [18][GP_STR], rows 0..111
    float2* Wt = Gp + FTILE2 * GP_STR;        // [24][18]

    const int m   = blockIdx.x;               // bin-triple 0..31
    const int fc0 = m * FTILE2;
    const int t0  = blockIdx.y * TTILE2;
    const int tid = threadIdx.x;

    for (int idx = tid; idx < 245 * 9; idx += 256) {
        int row = idx / 9, p = idx % 9;
        float4 v = *(const float4*)(g_g + (size_t)(t0 + row) * ECOLS + fc0 * 2 + p * 4);
        Gs[(2 * p) * GS_STR + row]     = make_float2(v.x, v.y);
        Gs[(2 * p + 1) * GS_STR + row] = make_float2(v.z, v.w);
    }
    for (int idx = tid; idx < 112 * 9; idx += 256) {
        int row = idx / 9, p = idx % 9;
        float4 v = *(const float4*)(g_g + (size_t)(t0 + 130 + row) * ECOLS + 1152 + fc0 * 2 + p * 4);
        Gp[(2 * p) * GP_STR + row]     = make_float2(v.x, v.y);
        Gp[(2 * p + 1) * GP_STR + row] = make_float2(v.z, v.w);
    }
    for (int idx = tid; idx < W2ROWS * 9; idx += 256) {
        int u = idx / 9, p = idx % 9;
        float4 v = *(const float4*)(g_w2 + u * 1152 + fc0 * 2 + p * 4);
        Wt[u * FTILE2 + 2 * p]     = make_float2(v.x, v.y);
        Wt[u * FTILE2 + 2 * p + 1] = make_float2(v.z, v.w);
    }
    __syncthreads();

    // ---- H phase: H[tau,f] = sum_{w<13} rho^w G[tau+w,f], rows 0..231 ----
    for (int cid = tid; cid < 522; cid += 256) {     // 18 f x 29 chunks of 8 rows
        int f = cid % 18, ch = cid / 18;
        int base = ch * 8;
        const float2* gb = Gs + f * GS_STR + base;
        unsigned long long gw[8], gsw[8], acc[8];
        #pragma unroll
        for (int r = 0; r < 8; r++) acc[r] = 0ULL;
        #pragma unroll
        for (int i = 0; i < 7; i++) {
            float2 g = gb[i];
            gw[i]  = pk2(g.x, g.y);
            gsw[i] = pk2(-g.y, g.x);
        }
        #pragma unroll
        for (int u = 0; u < 13; u++) {
            float2 g = gb[u + 7];
            gw[(u + 7) & 7]  = pk2(g.x, g.y);
            gsw[(u + 7) & 7] = pk2(-g.y, g.x);
            float2 wt = Wt[u * FTILE2 + f];
            unsigned long long wx = dup2(wt.x);
            unsigned long long wy = dup2(wt.y);
            #pragma unroll
            for (int r = 0; r < 8; r++) {
                fma2(acc[r], wx, gw[(u + r) & 7]);
                fma2(acc[r], wy, gsw[(u + r) & 7]);
            }
        }
        float2* hb = Hs + f * HS_STR + base;
        #pragma unroll
        for (int r = 0; r < 8; r++) hb[r] = upk2(acc[r]);
    }
    __syncthreads();

    // ---- Z phase ----
    const int f  = tid % 18;
    const int tg = tid / 18;
    const bool active = (tid < 252);
    const int base = tg * 8;
    unsigned long long acc[8] = {};
    if (active) {
        const float2* hb = Hs + f * HS_STR + base;
        #pragma unroll
        for (int v = 0; v < 10; v++) {
            float2 wt = Wt[(13 + v) * FTILE2 + f];
            unsigned long long wx = dup2(wt.x);
            unsigned long long wy = dup2(wt.y);
            #pragma unroll
            for (int r = 0; r < 8; r++) {
                float2 h = hb[13 * v + r];
                fma2(acc[r], wx, pk2(h.x, h.y));
                fma2(acc[r], wy, pk2(-h.y, h.x));
            }
        }
        float2 wt = Wt[23 * FTILE2 + f];
        unsigned long long wx = dup2(wt.x);
        unsigned long long wy = dup2(wt.y);
        const float2* gp = Gp + f * GP_STR + base;
        #pragma unroll
        for (int r = 0; r < 8; r++) {
            float2 g = gp[r];
            fma2(acc[r], wx, pk2(g.x, g.y));
            fma2(acc[r], wy, pk2(-g.y, g.x));
        }
    }
    __syncthreads();
    float2* Zs = Gs;
    if (active) {
        #pragma unroll
        for (int r = 0; r < 8; r++)
            Zs[f * ZS_STR + base + r] = upk2(acc[r]);
    }
    __syncthreads();

    // ---- combine triples -> power -> lerp -> log ----
    for (int idx = tid; idx < 3 * TTILE2; idx += 256) {
        int q  = idx / TTILE2;
        int tl = idx % TTILE2;
        int t  = t0 + tl;
        if (t >= T_FRAMES) continue;
        const float2* zq = Zs + (6 * q) * ZS_STR + tl;
        float2 z0 = zq[0];
        float2 z1 = zq[ZS_STR];
        float2 z2 = zq[2 * ZS_STR];
        float2 z3 = zq[3 * ZS_STR];
        float2 z4 = zq[4 * ZS_STR];
        float2 z5 = zq[5 * ZS_STR];
        float lre = z0.x + z1.x + z2.x, lim = z0.y + z1.y + z2.y;
        float hre = z3.x + z4.x + z5.x, him = z3.y + z4.y + z5.y;
        float plo = lre * lre + lim * lim;
        float phi = hre * hre + him * him;
        int bin = 3 * m + q;
        float al = g_alpha[bin];
        float p = (1.0f - al) * plo + al * phi;
        g_lpT[(size_t)bin * TPAD + t] = logf(fmaxf(p, 1e-8f));
    }
}

// ---------------- cep: DCT GEMM, 64-frame tiles ----------------
// grid 34 blocks x 256 thr. thread = (frame, 5-coeff group).
__global__ void __launch_bounds__(256) k_cep() {
    __shared__ float lps[NB * 64];            // [n][t] tile, 24 KB
    __shared__ float dctt[NC * NB];           // [c][n], 7.5 KB
    const int tid = threadIdx.x;
    const int t0 = blockIdx.x * 64;

    for (int idx = tid; idx < NB * 16; idx += 256) {
        int n = idx >> 4, p = idx & 15;
        float4 v = *(const float4*)(g_lpT + (size_t)n * TPAD + t0 + p * 4);
        *(float4*)(lps + n * 64 + p * 4) = v;
    }
    for (int idx = tid; idx < NC * NB; idx += 256) dctt[idx] = g_dct[idx];
    __syncthreads();

    const int t  = tid & 63;
    const int cg = tid >> 6;                  // 0..3
    const int c0 = cg * 5;
    float acc[5] = {};
    #pragma unroll 4
    for (int n = 0; n < NB; n++) {
        float v = lps[n * 64 + t];
        #pragma unroll
        for (int k = 0; k < 5; k++)
            acc[k] = fmaf(v, dctt[(c0 + k) * NB + n], acc[k]);
    }
    int tt = t0 + t;
    if (tt < T_FRAMES) {
        #pragma unroll
        for (int k = 0; k < 5; k++)
            g_c[tt * NC + c0 + k] = acc[k];
    }
}

// ---------------- fused normalize + delta + delta-delta ----------------
__global__ void __launch_bounds__(256) k_tail(float* __restrict__ out) {
    const int c = blockIdx.x;       // 0..19
    const int tid = threadIdx.x;
    __shared__ float cn[T_FRAMES];
    __shared__ float d1s[T_FRAMES];
    __shared__ float red[256];

    float s = 0.0f;
    for (int t = tid; t < T_FRAMES; t += 256) {
        float v = g_c[t * NC + c];
        cn[t] = v;
        s += v;
    }
    red[tid] = s; __syncthreads();
    for (int o = 128; o; o >>= 1) { if (tid < o) red[tid] += red[tid + o]; __syncthreads(); }
    float mean = red[0] / (float)T_FRAMES;
    __syncthreads();
    float ss = 0.0f;
    for (int t = tid; t < T_FRAMES; t += 256) { float d = cn[t] - mean; ss += d * d; }
    red[tid] = ss; __syncthreads();
    for (int o = 128; o; o >>= 1) { if (tid < o) red[tid] += red[tid + o]; __syncthreads(); }
    float inv = 1.0f / (sqrtf(red[0] / (float)(T_FRAMES - 1)) + 1e-8f);
    __syncthreads();
    for (int t = tid; t < T_FRAMES; t += 256) cn[t] = (cn[t] - mean) * inv;
    __syncthreads();

    for (int t = tid; t < T_FRAMES; t += 256) {
        int tp1 = min(t + 1, T_FRAMES - 1), tm1 = max(t - 1, 0);
        int tp2 = min(t + 2, T_FRAMES - 1), tm2 = max(t - 2, 0);
        float d = ((cn[tp1] - cn[tm1]) + 2.0f * (cn[tp2] - cn[tm2])) * 0.1f;
        d1s[t] = d;
        out[t * 60 + c]      = cn[t];
        out[t * 60 + 20 + c] = d;
    }
    __syncthreads();
    for (int t = tid; t < T_FRAMES; t += 256) {
        int tp1 = min(t + 1, T_FRAMES - 1), tm1 = max(t - 1, 0);
        int tp2 = min(t + 2, T_FRAMES - 1), tm2 = max(t - 2, 0);
        float d = ((d1s[tp1] - d1s[tm1]) + 2.0f * (d1s[tp2] - d1s[tm2])) * 0.1f;
        out[t * 60 + 40 + c] = d;
    }
}

// ---------------- launch ----------------
extern "C" void kernel_launch(void* const* d_in, const int* in_sizes, int n_in,
                              void* d_out, int out_size) {
    const float* wav = (const float*)d_in[0];
    float* out = (float*)d_out;

    const int s1_smem = (16384 + 128 * 64) * 4;   // 98304
    const int s2_smem = (FTILE2 * GS_STR + FTILE2 * HS_STR + FTILE2 * GP_STR
                         + W2ROWS * FTILE2) * 8;  // 88848
    cudaFuncSetAttribute(k_s1, cudaFuncAttributeMaxDynamicSharedMemorySize, s1_smem);
    cudaFuncSetAttribute(k_s2, cudaFuncAttributeMaxDynamicSharedMemorySize, s2_smem);

    k_setup<<<SETUP_BLKS, 256>>>(wav);
    k_s1<<<dim3(36, 18), 256, s1_smem>>>();
    k_s2<<<dim3(FB2, TT2), 256, s2_smem>>>();
    k_cep<<<TPAD / 64, 256>>>();
    k_tail<<<NC, 256>>>(out);
}

// round 12
// speedup vs baseline: 1.4067x; 1.1595x over previous
#include <cuda_runtime.h>
#include <cstdint>

// ---------------- constants ----------------
#define T_FRAMES 2049
#define NWAV     262144
#define MW       16699
#define LEFT     24418
#define PADR     32768
#define NB       96
#define NC       20
#define NPAIR    96
#define EC2      1152           // [full 576 | partial 576] moment cols
#define GROWS    2368
#define XW_LEN   294912         // 2304*128
#define TPAD     2176

// stage-2 tiling
#define FTILE2   18
#define TTILE2   112
#define TT2      19
#define FB2      32
#define GS_STR   247
#define HS_STR   233
#define MP_STR   113
#define ZS_STR   113
#define W2ROWS   24

// setup kernel block ranges
#define PAD_BLKS 1152
#define E_BLKS   288            // 576 colpairs, 2 per block
#define NF       576
#define W_ELEMS  (NF * W2ROWS)
#define W_BLKS   54
#define SETUP_BLKS (PAD_BLKS + E_BLKS + W_BLKS + 1)

// ---------------- device scratch ----------------
__device__ float g_xw[XW_LEN];
__device__ float g_e[128 * EC2];
__device__ float g_w2[W2ROWS * 1152];
__device__ float g_g[(size_t)GROWS * EC2];
__device__ float g_lpT[(size_t)NB * TPAD];      // log cqt power, [bin][t]
__device__ float g_c[T_FRAMES * NC];
__device__ float g_alpha[NB];
__device__ float g_dct[NC * NB];

// ---------------- f32x2 helpers ----------------
__device__ __forceinline__ void fma2(unsigned long long& acc,
                                     unsigned long long a, unsigned long long b) {
    asm("fma.rn.f32x2 %0, %1, %2, %0;" : "+l"(acc) : "l"(a), "l"(b));
}
__device__ __forceinline__ unsigned long long dup2(float x) {
    unsigned long long r;
    asm("mov.b64 %0, {%1, %1};" : "=l"(r) : "f"(x));
    return r;
}
__device__ __forceinline__ unsigned long long pk2(float x, float y) {
    unsigned long long r;
    asm("mov.b64 %0, {%1, %2};" : "=l"(r) : "f"(x), "f"(y));
    return r;
}
__device__ __forceinline__ float2 upk2(unsigned long long v) {
    float2 r;
    asm("mov.b64 {%0, %1}, %2;" : "=f"(r.x), "=f"(r.y) : "l"(v));
    return r;
}

// ---------------- inline bin computation ----------------
__device__ __forceinline__ int bin_of(int bi) {   // bi 0..191
    int i = bi >> 1;
    float cq   = 32.7f * exp2f((float)i / 24.0f);
    float idxf = cq / 8000.0f * 32768.0f;
    int lo = (int)idxf;
    lo = max(0, min(lo, 32767));
    return lo + (bi & 1);
}

// rho offset for local freq index fi (0..17 within block; same for all blocks)
__device__ __forceinline__ float rho_of(int fi) {
    int bl = fi / 3, j = fi - 3 * bl;
    int h = bl & 1;
    float sgn = (j == 1) ? -1.0f : (j == 2) ? 1.0f : 0.0f;
    return 6.283185307f * ((h ? 0.5f : -0.5f) * (1.0f / 65536.0f) + sgn * (1.0f / (float)MW));
}

// ---------------- fused setup ----------------
__global__ void __launch_bounds__(256) k_setup(const float* __restrict__ wav) {
    const int blk = blockIdx.x;
    const int tid = threadIdx.x;

    if (blk < PAD_BLKS) {
        int i = blk * 256 + tid;
        int q = i + (LEFT - PADR);
        int idx = (q < 0) ? -q : ((q >= NWAV) ? (2 * NWAV - 2 - q) : q);
        idx = max(0, min(idx, NWAV - 1));
        g_xw[i] = wav[idx];
        return;
    }
    if (blk < PAD_BLKS + E_BLKS) {
        // moment basis: E_m[r, pair] = r^m * e^{-i theta_c r}, theta_c = pi(2b_lo+1)/65536
        int e = (blk - PAD_BLKS) * 2 + (tid >> 7);   // 0..575
        int r = tid & 127;
        int part = (e >= 288);
        int e2 = part ? e - 288 : e;
        int p = e2 / 3, mm = e2 % 3;
        int b = bin_of(2 * p);                       // lo bin of pair
        int mod = ((2 * b + 1) * r) & 131071;
        float x = (float)mod * (1.0f / 65536.0f);
        if (x >= 1.0f) x -= 2.0f;
        float s, c;
        sincospif(x, &s, &c);
        float pw = (mm == 0) ? 1.0f : (mm == 1) ? (float)r : (float)(r * r);
        float re = pw * c, im = -pw * s;
        if (part && r >= 59) { re = 0.0f; im = 0.0f; }
        int col = (part ? 576 : 0) + p * 6 + mm * 2;
        g_e[r * EC2 + col]     = re;
        g_e[r * EC2 + col + 1] = im;
        return;
    }
    if (blk < PAD_BLKS + E_BLKS + W_BLKS) {
        int lin = (blk - PAD_BLKS - E_BLKS) * 256 + tid;
        if (lin >= W_ELEMS) return;
        int fi = lin / W2ROWS;
        int u  = lin % W2ROWS;
        int bi = fi / 3, j = fi % 3;
        int b  = bin_of(bi);
        int sgn = (j == 1) ? -1 : (j == 2) ? 1 : 0;
        float wre, wim;
        if (u < 13) {
            float fa = (float)((b * u) & 511) * (1.0f / 512.0f);
            float fbv = (float)(128 * u) * (1.0f / (float)MW);
            float fr = fa + (float)sgn * fbv;
            float s, c;
            sincospif(2.0f * fr, &s, &c);
            wre = c; wim = -s;
        } else {
            float coeff = (j == 0) ? 0.5f : -0.25f;
            int e = (u < 23) ? 13 * (u - 13) : 130;
            float fa = (float)((b * e) & 511) * (1.0f / 512.0f);
            float fbv = (float)((128 * e) % MW) * (1.0f / (float)MW);
            float fr = fa + (float)sgn * fbv;
            float s, c;
            sincospif(2.0f * fr, &s, &c);
            wre = coeff * c;
            wim = -coeff * s;
        }
        g_w2[u * 1152 + 2 * fi]     = wre;
        g_w2[u * 1152 + 2 * fi + 1] = wim;
        return;
    }
    // last block: alpha + dct
    if (tid < NB) {
        float cq   = 32.7f * exp2f((float)tid / 24.0f);
        float idxf = cq / 8000.0f * 32768.0f;
        int lo = (int)idxf;
        lo = max(0, min(lo, 32767));
        g_alpha[tid] = idxf - (float)lo;
    }
    for (int idx = tid; idx < NC * NB; idx += 256) {
        int c = idx / NB, n = idx % NB;
        g_dct[idx] = cospif((float)(c * (2 * n + 1)) / 192.0f);
    }
}

// ---------------- stage 1: moment GEMM, block 128 rows x 64 cols ----------------
__global__ void __launch_bounds__(256) k_s1() {
    extern __shared__ float smem[];
    float* xs = smem;            // 16384 floats
    float* ts = smem + 16384;    // up to 128 x 64

    const int bx = blockIdx.x;                 // 0..17
    const int c0 = (bx < 9) ? bx * 64 : 576 + (bx - 9) * 64;
    const int K  = (bx < 9) ? 128 : 64;
    const int s0 = blockIdx.y * 128;
    const int tid = threadIdx.x;
    const int cg = tid & 15;
    const int fg = tid >> 4;

    const float4* xsrc = (const float4*)(g_xw + s0 * 128);
    #pragma unroll
    for (int i = tid; i < 4096; i += 256)
        ((float4*)xs)[i] = xsrc[i];
    for (int i = tid; i < K * 16; i += 256) {
        int kk = i >> 4, c4 = i & 15;
        ((float4*)ts)[i] = *(const float4*)(g_e + kk * EC2 + c0 + c4 * 4);
    }
    __syncthreads();

    unsigned long long acc[8][2] = {};
    for (int kk0 = 0; kk0 < K; kk0 += 4) {
        float4 af[8];
        #pragma unroll
        for (int r = 0; r < 8; r++)
            af[r] = *(const float4*)(xs + (fg * 8 + r) * 128 + kk0);
        #pragma unroll
        for (int k = 0; k < 4; k++) {
            ulonglong2 bb = *(const ulonglong2*)(ts + (kk0 + k) * 64 + cg * 4);
            #pragma unroll
            for (int r = 0; r < 8; r++) {
                unsigned long long ad = dup2(((const float*)&af[r])[k]);
                fma2(acc[r][0], ad, bb.x);
                fma2(acc[r][1], ad, bb.y);
            }
        }
    }

    #pragma unroll
    for (int r = 0; r < 8; r++) {
        int s = s0 + fg * 8 + r;
        ulonglong2 v;
        v.x = acc[r][0]; v.y = acc[r][1];
        *(ulonglong2*)(g_g + (size_t)s * EC2 + c0 + cg * 4) = v;
    }
}

// ---------------- stage 2: moment expand + two-level FIR + fused power/log ----------------
__global__ void __launch_bounds__(256) k_s2() {
    extern __shared__ float smem[];
    float2* Gs = (float2*)smem;               // [18][GS_STR]
    float2* Hs = Gs + FTILE2 * GS_STR;        // [18][HS_STR]; first used as Ms[9][GS_STR]
    float2* Mp = Hs + FTILE2 * HS_STR;        // [9][MP_STR]
    float2* Wt = Mp + 9 * MP_STR;             // [24][18]

    const int m   = blockIdx.x;               // bin-triple 0..31
    const int t0  = blockIdx.y * TTILE2;
    const int tid = threadIdx.x;
    float2* Ms = Hs;                          // alias while loading

    for (int idx = tid; idx < 245 * 9; idx += 256) {
        int row = idx / 9, q = idx % 9;
        Ms[q * GS_STR + row] = *(const float2*)(g_g + (size_t)(t0 + row) * EC2 + 18 * m + 2 * q);
    }
    for (int idx = tid; idx < 112 * 9; idx += 256) {
        int row = idx / 9, q = idx % 9;
        Mp[q * MP_STR + row] = *(const float2*)(g_g + (size_t)(t0 + 130 + row) * EC2 + 576 + 18 * m + 2 * q);
    }
    for (int idx = tid; idx < W2ROWS * 9; idx += 256) {
        int u = idx / 9, p = idx % 9;
        float4 v = *(const float4*)(g_w2 + u * 1152 + m * FTILE2 * 2 + p * 4);
        Wt[u * FTILE2 + 2 * p]     = make_float2(v.x, v.y);
        Wt[u * FTILE2 + 2 * p + 1] = make_float2(v.z, v.w);
    }
    __syncthreads();

    // ---- expand moments -> Gs (2nd-order Taylor) ----
    for (int idx = tid; idx < 245 * 18; idx += 256) {
        int fi = idx % 18, row = idx / 18;
        int pp = (fi / 3) >> 1;
        float rho = rho_of(fi);
        float r2 = 0.5f * rho * rho;
        float2 m0 = Ms[(pp * 3 + 0) * GS_STR + row];
        float2 m1 = Ms[(pp * 3 + 1) * GS_STR + row];
        float2 m2 = Ms[(pp * 3 + 2) * GS_STR + row];
        float2 g;
        g.x = m0.x + rho * m1.y - r2 * m2.x;
        g.y = m0.y - rho * m1.x - r2 * m2.y;
        Gs[fi * GS_STR + row] = g;
    }
    __syncthreads();

    // ---- H phase: H[tau,f] = sum_{w<13} rho^w G[tau+w,f], rows 0..231 ----
    for (int cid = tid; cid < 522; cid += 256) {     // 18 f x 29 chunks of 8 rows
        int f = cid % 18, ch = cid / 18;
        int base = ch * 8;
        const float2* gb = Gs + f * GS_STR + base;
        unsigned long long gw[8], gsw[8], acc[8];
        #pragma unroll
        for (int r = 0; r < 8; r++) acc[r] = 0ULL;
        #pragma unroll
        for (int i = 0; i < 7; i++) {
            float2 g = gb[i];
            gw[i]  = pk2(g.x, g.y);
            gsw[i] = pk2(-g.y, g.x);
        }
        #pragma unroll
        for (int u = 0; u < 13; u++) {
            float2 g = gb[u + 7];
            gw[(u + 7) & 7]  = pk2(g.x, g.y);
            gsw[(u + 7) & 7] = pk2(-g.y, g.x);
            float2 wt = Wt[u * FTILE2 + f];
            unsigned long long wx = dup2(wt.x);
            unsigned long long wy = dup2(wt.y);
            #pragma unroll
            for (int r = 0; r < 8; r++) {
                fma2(acc[r], wx, gw[(u + r) & 7]);
                fma2(acc[r], wy, gsw[(u + r) & 7]);
            }
        }
        float2* hb = Hs + f * HS_STR + base;
        #pragma unroll
        for (int r = 0; r < 8; r++) hb[r] = upk2(acc[r]);
    }
    __syncthreads();

    // ---- Z phase: 10 coarse taps on H + 3 partial taps on Mp ----
    const int f  = tid % 18;
    const int tg = tid / 18;
    const bool active = (tid < 252);
    const int base = tg * 8;
    unsigned long long acc[8] = {};
    if (active) {
        const float2* hb = Hs + f * HS_STR + base;
        #pragma unroll
        for (int v = 0; v < 10; v++) {
            float2 wt = Wt[(13 + v) * FTILE2 + f];
            unsigned long long wx = dup2(wt.x);
            unsigned long long wy = dup2(wt.y);
            #pragma unroll
            for (int r = 0; r < 8; r++) {
                float2 h = hb[13 * v + r];
                fma2(acc[r], wx, pk2(h.x, h.y));
                fma2(acc[r], wy, pk2(-h.y, h.x));
            }
        }
        // partial: taps w, -i*rho*w, -rho^2/2*w on moment streams
        float2 wt = Wt[23 * FTILE2 + f];
        float rho = rho_of(f);
        float r2 = 0.5f * rho * rho;
        float2 W[3];
        W[0] = wt;
        W[1] = make_float2(rho * wt.y, -rho * wt.x);
        W[2] = make_float2(-r2 * wt.x, -r2 * wt.y);
        int pp = (f / 3) >> 1;
        #pragma unroll
        for (int mm = 0; mm < 3; mm++) {
            unsigned long long wx = dup2(W[mm].x);
            unsigned long long wy = dup2(W[mm].y);
            const float2* gp = Mp + (pp * 3 + mm) * MP_STR + base;
            #pragma unroll
            for (int r = 0; r < 8; r++) {
                float2 g = gp[r];
                fma2(acc[r], wx, pk2(g.x, g.y));
                fma2(acc[r], wy, pk2(-g.y, g.x));
            }
        }
    }
    __syncthreads();
    float2* Zs = Gs;
    if (active) {
        #pragma unroll
        for (int r = 0; r < 8; r++)
            Zs[f * ZS_STR + base + r] = upk2(acc[r]);
    }
    __syncthreads();

    // ---- combine triples -> power -> lerp -> log ----
    for (int idx = tid; idx < 3 * TTILE2; idx += 256) {
        int q  = idx / TTILE2;
        int tl = idx % TTILE2;
        int t  = t0 + tl;
        if (t >= T_FRAMES) continue;
        const float2* zq = Zs + (6 * q) * ZS_STR + tl;
        float2 z0 = zq[0];
        float2 z1 = zq[ZS_STR];
        float2 z2 = zq[2 * ZS_STR];
        float2 z3 = zq[3 * ZS_STR];
        float2 z4 = zq[4 * ZS_STR];
        float2 z5 = zq[5 * ZS_STR];
        float lre = z0.x + z1.x + z2.x, lim = z0.y + z1.y + z2.y;
        float hre = z3.x + z4.x + z5.x, him = z3.y + z4.y + z5.y;
        float plo = lre * lre + lim * lim;
        float phi = hre * hre + him * him;
        int bin = 3 * m + q;
        float al = g_alpha[bin];
        float p = (1.0f - al) * plo + al * phi;
        g_lpT[(size_t)bin * TPAD + t] = logf(fmaxf(p, 1e-8f));
    }
}

// ---------------- cep: DCT GEMM, 32-frame tiles (68 blocks) ----------------
__global__ void __launch_bounds__(256) k_cep() {
    __shared__ float lps[NB * 32];            // [n][t]
    __shared__ float dctt[24 * NB];           // padded [c][n]
    const int tid = threadIdx.x;
    const int t0 = blockIdx.x * 32;

    for (int idx = tid; idx < NB * 8; idx += 256) {
        int n = idx >> 3, p = idx & 7;
        float4 v = *(const float4*)(g_lpT + (size_t)n * TPAD + t0 + p * 4);
        *(float4*)(lps + n * 32 + p * 4) = v;
    }
    for (int idx = tid; idx < 24 * NB; idx += 256)
        dctt[idx] = (idx < NC * NB) ? g_dct[idx] : 0.0f;
    __syncthreads();

    const int t  = tid & 31;
    const int cg = tid >> 5;                  // 0..7
    const int c0 = cg * 3;
    float acc[3] = {};
    #pragma unroll 4
    for (int n = 0; n < NB; n++) {
        float v = lps[n * 32 + t];
        #pragma unroll
        for (int k = 0; k < 3; k++)
            acc[k] = fmaf(v, dctt[(c0 + k) * NB + n], acc[k]);
    }
    int tt = t0 + t;
    if (tt < T_FRAMES) {
        #pragma unroll
        for (int k = 0; k < 3; k++)
            if (c0 + k < NC) g_c[tt * NC + c0 + k] = acc[k];
    }
}

// ---------------- fused normalize + delta + delta-delta ----------------
__global__ void __launch_bounds__(256) k_tail(float* __restrict__ out) {
    const int c = blockIdx.x;       // 0..19
    const int tid = threadIdx.x;
    __shared__ float cn[T_FRAMES];
    __shared__ float d1s[T_FRAMES];
    __shared__ float red[256];

    float s = 0.0f;
    for (int t = tid; t < T_FRAMES; t += 256) {
        float v = g_c[t * NC + c];
        cn[t] = v;
        s += v;
    }
    red[tid] = s; __syncthreads();
    for (int o = 128; o; o >>= 1) { if (tid < o) red[tid] += red[tid + o]; __syncthreads(); }
    float mean = red[0] / (float)T_FRAMES;
    __syncthreads();
    float ss = 0.0f;
    for (int t = tid; t < T_FRAMES; t += 256) { float d = cn[t] - mean; ss += d * d; }
    red[tid] = ss; __syncthreads();
    for (int o = 128; o; o >>= 1) { if (tid < o) red[tid] += red[tid + o]; __syncthreads(); }
    float inv = 1.0f / (sqrtf(red[0] / (float)(T_FRAMES - 1)) + 1e-8f);
    __syncthreads();
    for (int t = tid; t < T_FRAMES; t += 256) cn[t] = (cn[t] - mean) * inv;
    __syncthreads();

    for (int t = tid; t < T_FRAMES; t += 256) {
        int tp1 = min(t + 1, T_FRAMES - 1), tm1 = max(t - 1, 0);
        int tp2 = min(t + 2, T_FRAMES - 1), tm2 = max(t - 2, 0);
        float d = ((cn[tp1] - cn[tm1]) + 2.0f * (cn[tp2] - cn[tm2])) * 0.1f;
        d1s[t] = d;
        out[t * 60 + c]      = cn[t];
        out[t * 60 + 20 + c] = d;
    }
    __syncthreads();
    for (int t = tid; t < T_FRAMES; t += 256) {
        int tp1 = min(t + 1, T_FRAMES - 1), tm1 = max(t - 1, 0);
        int tp2 = min(t + 2, T_FRAMES - 1), tm2 = max(t - 2, 0);
        float d = ((d1s[tp1] - d1s[tm1]) + 2.0f * (d1s[tp2] - d1s[tm2])) * 0.1f;
        out[t * 60 + 40 + c] = d;
    }
}

// ---------------- launch ----------------
extern "C" void kernel_launch(void* const* d_in, const int* in_sizes, int n_in,
                              void* d_out, int out_size) {
    const float* wav = (const float*)d_in[0];
    float* out = (float*)d_out;

    const int s1_smem = (16384 + 128 * 64) * 4;   // 98304
    const int s2_smem = (FTILE2 * GS_STR + FTILE2 * HS_STR + 9 * MP_STR
                         + W2ROWS * FTILE2) * 8;  // 80712
    cudaFuncSetAttribute(k_s1, cudaFuncAttributeMaxDynamicSharedMemorySize, s1_smem);
    cudaFuncSetAttribute(k_s2, cudaFuncAttributeMaxDynamicSharedMemorySize, s2_smem);

    k_setup<<<SETUP_BLKS, 256>>>(wav);
    k_s1<<<dim3(18, 18), 256, s1_smem>>>();
    k_s2<<<dim3(FB2, TT2), 256, s2_smem>>>();
    k_cep<<<TPAD / 32, 256>>>();
    k_tail<<<NC, 256>>>(out);
}

// round 13
// speedup vs baseline: 1.4156x; 1.0063x over previous
#include <cuda_runtime.h>
#include <cstdint>

// ---------------- constants ----------------
#define T_FRAMES 2049
#define NWAV     262144
#define MW       16699
#define LEFT     24418
#define PADR     32768
#define NB       96
#define NC       20
#define NPAIR    96
#define EC2      1152           // [full 576 | partial 576] moment cols
#define GROWS    2368
#define XW_LEN   294912         // 2304*128
#define TPAD     2176

// stage-2 tiling
#define FTILE2   18
#define TTILE2   112
#define TT2      19
#define FB2      32
#define GS_STR   247
#define HS_STR   233
#define MP_STR   113
#define ZS_STR   113
#define W2ROWS   24

// setup kernel block ranges
#define PAD_BLKS 1152
#define E_BLKS   288            // 576 colpairs, 2 per block
#define NF       576
#define W_ELEMS  (NF * W2ROWS)
#define W_BLKS   54
#define SETUP_BLKS (PAD_BLKS + E_BLKS + W_BLKS + 1)

// ---------------- device scratch ----------------
__device__ float g_xw[XW_LEN];
__device__ float g_e[128 * EC2];
__device__ float g_w2[W2ROWS * 1152];
__device__ float g_g[(size_t)GROWS * EC2];
__device__ float g_lpT[(size_t)NB * TPAD];      // log cqt power, [bin][t]
__device__ float g_c[NC * TPAD];                // cepstra, [c][t]
__device__ float g_alpha[NB];
__device__ float g_dct[NC * NB];

// ---------------- f32x2 helpers ----------------
__device__ __forceinline__ void fma2(unsigned long long& acc,
                                     unsigned long long a, unsigned long long b) {
    asm("fma.rn.f32x2 %0, %1, %2, %0;" : "+l"(acc) : "l"(a), "l"(b));
}
__device__ __forceinline__ unsigned long long dup2(float x) {
    unsigned long long r;
    asm("mov.b64 %0, {%1, %1};" : "=l"(r) : "f"(x));
    return r;
}
__device__ __forceinline__ unsigned long long pk2(float x, float y) {
    unsigned long long r;
    asm("mov.b64 %0, {%1, %2};" : "=l"(r) : "f"(x), "f"(y));
    return r;
}
__device__ __forceinline__ float2 upk2(unsigned long long v) {
    float2 r;
    asm("mov.b64 {%0, %1}, %2;" : "=f"(r.x), "=f"(r.y) : "l"(v));
    return r;
}

// ---------------- inline bin computation ----------------
__device__ __forceinline__ int bin_of(int bi) {   // bi 0..191
    int i = bi >> 1;
    float cq   = 32.7f * exp2f((float)i / 24.0f);
    float idxf = cq / 8000.0f * 32768.0f;
    int lo = (int)idxf;
    lo = max(0, min(lo, 32767));
    return lo + (bi & 1);
}

// rho offset for local freq index fi (0..17 within block; same for all blocks)
__device__ __forceinline__ float rho_of(int fi) {
    int bl = fi / 3, j = fi - 3 * bl;
    int h = bl & 1;
    float sgn = (j == 1) ? -1.0f : (j == 2) ? 1.0f : 0.0f;
    return 6.283185307f * ((h ? 0.5f : -0.5f) * (1.0f / 65536.0f) + sgn * (1.0f / (float)MW));
}

// ---------------- fused setup ----------------
__global__ void __launch_bounds__(256) k_setup(const float* __restrict__ wav) {
    const int blk = blockIdx.x;
    const int tid = threadIdx.x;

    if (blk < PAD_BLKS) {
        int i = blk * 256 + tid;
        int q = i + (LEFT - PADR);
        int idx = (q < 0) ? -q : ((q >= NWAV) ? (2 * NWAV - 2 - q) : q);
        idx = max(0, min(idx, NWAV - 1));
        g_xw[i] = wav[idx];
        return;
    }
    if (blk < PAD_BLKS + E_BLKS) {
        // moment basis: E_m[r, pair] = r^m * e^{-i theta_c r}, theta_c = pi(2b_lo+1)/65536
        int e = (blk - PAD_BLKS) * 2 + (tid >> 7);   // 0..575
        int r = tid & 127;
        int part = (e >= 288);
        int e2 = part ? e - 288 : e;
        int p = e2 / 3, mm = e2 % 3;
        int b = bin_of(2 * p);                       // lo bin of pair
        int mod = ((2 * b + 1) * r) & 131071;
        float x = (float)mod * (1.0f / 65536.0f);
        if (x >= 1.0f) x -= 2.0f;
        float s, c;
        sincospif(x, &s, &c);
        float pw = (mm == 0) ? 1.0f : (mm == 1) ? (float)r : (float)(r * r);
        float re = pw * c, im = -pw * s;
        if (part && r >= 59) { re = 0.0f; im = 0.0f; }
        int col = (part ? 576 : 0) + p * 6 + mm * 2;
        g_e[r * EC2 + col]     = re;
        g_e[r * EC2 + col + 1] = im;
        return;
    }
    if (blk < PAD_BLKS + E_BLKS + W_BLKS) {
        int lin = (blk - PAD_BLKS - E_BLKS) * 256 + tid;
        if (lin >= W_ELEMS) return;
        int fi = lin / W2ROWS;
        int u  = lin % W2ROWS;
        int bi = fi / 3, j = fi % 3;
        int b  = bin_of(bi);
        int sgn = (j == 1) ? -1 : (j == 2) ? 1 : 0;
        float wre, wim;
        if (u < 13) {
            float fa = (float)((b * u) & 511) * (1.0f / 512.0f);
            float fbv = (float)(128 * u) * (1.0f / (float)MW);
            float fr = fa + (float)sgn * fbv;
            float s, c;
            sincospif(2.0f * fr, &s, &c);
            wre = c; wim = -s;
        } else {
            float coeff = (j == 0) ? 0.5f : -0.25f;
            int e = (u < 23) ? 13 * (u - 13) : 130;
            float fa = (float)((b * e) & 511) * (1.0f / 512.0f);
            float fbv = (float)((128 * e) % MW) * (1.0f / (float)MW);
            float fr = fa + (float)sgn * fbv;
            float s, c;
            sincospif(2.0f * fr, &s, &c);
            wre = coeff * c;
            wim = -coeff * s;
        }
        g_w2[u * 1152 + 2 * fi]     = wre;
        g_w2[u * 1152 + 2 * fi + 1] = wim;
        return;
    }
    // last block: alpha + dct
    if (tid < NB) {
        float cq   = 32.7f * exp2f((float)tid / 24.0f);
        float idxf = cq / 8000.0f * 32768.0f;
        int lo = (int)idxf;
        lo = max(0, min(lo, 32767));
        g_alpha[tid] = idxf - (float)lo;
    }
    for (int idx = tid; idx < NC * NB; idx += 256) {
        int c = idx / NB, n = idx % NB;
        g_dct[idx] = cospif((float)(c * (2 * n + 1)) / 192.0f);
    }
}

// ---------------- stage 1: moment GEMM, block 128 rows x 64 cols ----------------
__global__ void __launch_bounds__(256) k_s1() {
    extern __shared__ float smem[];
    float* xs = smem;            // 16384 floats
    float* ts = smem + 16384;    // up to 128 x 64

    const int bx = blockIdx.x;                 // 0..17
    const int c0 = (bx < 9) ? bx * 64 : 576 + (bx - 9) * 64;
    const int K  = (bx < 9) ? 128 : 64;
    const int s0 = blockIdx.y * 128;
    const int tid = threadIdx.x;
    const int cg = tid & 15;
    const int fg = tid >> 4;

    const float4* xsrc = (const float4*)(g_xw + s0 * 128);
    #pragma unroll
    for (int i = tid; i < 4096; i += 256)
        ((float4*)xs)[i] = xsrc[i];
    for (int i = tid; i < K * 16; i += 256) {
        int kk = i >> 4, c4 = i & 15;
        ((float4*)ts)[i] = *(const float4*)(g_e + kk * EC2 + c0 + c4 * 4);
    }
    __syncthreads();

    unsigned long long acc[8][2] = {};
    for (int kk0 = 0; kk0 < K; kk0 += 4) {
        float4 af[8];
        #pragma unroll
        for (int r = 0; r < 8; r++)
            af[r] = *(const float4*)(xs + (fg * 8 + r) * 128 + kk0);
        #pragma unroll
        for (int k = 0; k < 4; k++) {
            ulonglong2 bb = *(const ulonglong2*)(ts + (kk0 + k) * 64 + cg * 4);
            #pragma unroll
            for (int r = 0; r < 8; r++) {
                unsigned long long ad = dup2(((const float*)&af[r])[k]);
                fma2(acc[r][0], ad, bb.x);
                fma2(acc[r][1], ad, bb.y);
            }
        }
    }

    #pragma unroll
    for (int r = 0; r < 8; r++) {
        int s = s0 + fg * 8 + r;
        ulonglong2 v;
        v.x = acc[r][0]; v.y = acc[r][1];
        *(ulonglong2*)(g_g + (size_t)s * EC2 + c0 + cg * 4) = v;
    }
}

// ---------------- stage 2: moment expand + two-level FIR + fused power/log ----------------
__global__ void __launch_bounds__(256) k_s2() {
    extern __shared__ float smem[];
    float2* Gs = (float2*)smem;               // [18][GS_STR]
    float2* Hs = Gs + FTILE2 * GS_STR;        // [18][HS_STR]; first used as Ms[9][GS_STR]
    float2* Mp = Hs + FTILE2 * HS_STR;        // [9][MP_STR]
    float2* Wt = Mp + 9 * MP_STR;             // [24][18]

    const int m   = blockIdx.x;               // bin-triple 0..31
    const int t0  = blockIdx.y * TTILE2;
    const int tid = threadIdx.x;
    float2* Ms = Hs;                          // alias while loading

    for (int idx = tid; idx < 245 * 9; idx += 256) {
        int row = idx / 9, q = idx % 9;
        Ms[q * GS_STR + row] = *(const float2*)(g_g + (size_t)(t0 + row) * EC2 + 18 * m + 2 * q);
    }
    for (int idx = tid; idx < 112 * 9; idx += 256) {
        int row = idx / 9, q = idx % 9;
        Mp[q * MP_STR + row] = *(const float2*)(g_g + (size_t)(t0 + 130 + row) * EC2 + 576 + 18 * m + 2 * q);
    }
    for (int idx = tid; idx < W2ROWS * 9; idx += 256) {
        int u = idx / 9, p = idx % 9;
        float4 v = *(const float4*)(g_w2 + u * 1152 + m * FTILE2 * 2 + p * 4);
        Wt[u * FTILE2 + 2 * p]     = make_float2(v.x, v.y);
        Wt[u * FTILE2 + 2 * p + 1] = make_float2(v.z, v.w);
    }
    __syncthreads();

    // ---- expand moments -> Gs (2nd-order Taylor) ----
    for (int idx = tid; idx < 245 * 18; idx += 256) {
        int fi = idx % 18, row = idx / 18;
        int pp = (fi / 3) >> 1;
        float rho = rho_of(fi);
        float r2 = 0.5f * rho * rho;
        float2 m0 = Ms[(pp * 3 + 0) * GS_STR + row];
        float2 m1 = Ms[(pp * 3 + 1) * GS_STR + row];
        float2 m2 = Ms[(pp * 3 + 2) * GS_STR + row];
        float2 g;
        g.x = m0.x + rho * m1.y - r2 * m2.x;
        g.y = m0.y - rho * m1.x - r2 * m2.y;
        Gs[fi * GS_STR + row] = g;
    }
    __syncthreads();

    // ---- H phase: H[tau,f] = sum_{w<13} rho^w G[tau+w,f], rows 0..231 ----
    for (int cid = tid; cid < 522; cid += 256) {     // 18 f x 29 chunks of 8 rows
        int f = cid % 18, ch = cid / 18;
        int base = ch * 8;
        const float2* gb = Gs + f * GS_STR + base;
        unsigned long long gw[8], gsw[8], acc[8];
        #pragma unroll
        for (int r = 0; r < 8; r++) acc[r] = 0ULL;
        #pragma unroll
        for (int i = 0; i < 7; i++) {
            float2 g = gb[i];
            gw[i]  = pk2(g.x, g.y);
            gsw[i] = pk2(-g.y, g.x);
        }
        #pragma unroll
        for (int u = 0; u < 13; u++) {
            float2 g = gb[u + 7];
            gw[(u + 7) & 7]  = pk2(g.x, g.y);
            gsw[(u + 7) & 7] = pk2(-g.y, g.x);
            float2 wt = Wt[u * FTILE2 + f];
            unsigned long long wx = dup2(wt.x);
            unsigned long long wy = dup2(wt.y);
            #pragma unroll
            for (int r = 0; r < 8; r++) {
                fma2(acc[r], wx, gw[(u + r) & 7]);
                fma2(acc[r], wy, gsw[(u + r) & 7]);
            }
        }
        float2* hb = Hs + f * HS_STR + base;
        #pragma unroll
        for (int r = 0; r < 8; r++) hb[r] = upk2(acc[r]);
    }
    __syncthreads();

    // ---- Z phase: 10 coarse taps on H + 3 partial taps on Mp ----
    const int f  = tid % 18;
    const int tg = tid / 18;
    const bool active = (tid < 252);
    const int base = tg * 8;
    unsigned long long acc[8] = {};
    if (active) {
        const float2* hb = Hs + f * HS_STR + base;
        #pragma unroll
        for (int v = 0; v < 10; v++) {
            float2 wt = Wt[(13 + v) * FTILE2 + f];
            unsigned long long wx = dup2(wt.x);
            unsigned long long wy = dup2(wt.y);
            #pragma unroll
            for (int r = 0; r < 8; r++) {
                float2 h = hb[13 * v + r];
                fma2(acc[r], wx, pk2(h.x, h.y));
                fma2(acc[r], wy, pk2(-h.y, h.x));
            }
        }
        // partial: taps w, -i*rho*w, -rho^2/2*w on moment streams
        float2 wt = Wt[23 * FTILE2 + f];
        float rho = rho_of(f);
        float r2 = 0.5f * rho * rho;
        float2 W[3];
        W[0] = wt;
        W[1] = make_float2(rho * wt.y, -rho * wt.x);
        W[2] = make_float2(-r2 * wt.x, -r2 * wt.y);
        int pp = (f / 3) >> 1;
        #pragma unroll
        for (int mm = 0; mm < 3; mm++) {
            unsigned long long wx = dup2(W[mm].x);
            unsigned long long wy = dup2(W[mm].y);
            const float2* gp = Mp + (pp * 3 + mm) * MP_STR + base;
            #pragma unroll
            for (int r = 0; r < 8; r++) {
                float2 g = gp[r];
                fma2(acc[r], wx, pk2(g.x, g.y));
                fma2(acc[r], wy, pk2(-g.y, g.x));
            }
        }
    }
    __syncthreads();
    float2* Zs = Gs;
    if (active) {
        #pragma unroll
        for (int r = 0; r < 8; r++)
            Zs[f * ZS_STR + base + r] = upk2(acc[r]);
    }
    __syncthreads();

    // ---- combine triples -> power -> lerp -> log ----
    for (int idx = tid; idx < 3 * TTILE2; idx += 256) {
        int q  = idx / TTILE2;
        int tl = idx % TTILE2;
        int t  = t0 + tl;
        if (t >= T_FRAMES) continue;
        const float2* zq = Zs + (6 * q) * ZS_STR + tl;
        float2 z0 = zq[0];
        float2 z1 = zq[ZS_STR];
        float2 z2 = zq[2 * ZS_STR];
        float2 z3 = zq[3 * ZS_STR];
        float2 z4 = zq[4 * ZS_STR];
        float2 z5 = zq[5 * ZS_STR];
        float lre = z0.x + z1.x + z2.x, lim = z0.y + z1.y + z2.y;
        float hre = z3.x + z4.x + z5.x, him = z3.y + z4.y + z5.y;
        float plo = lre * lre + lim * lim;
        float phi = hre * hre + him * him;
        int bin = 3 * m + q;
        float al = g_alpha[bin];
        float p = (1.0f - al) * plo + al * phi;
        g_lpT[(size_t)bin * TPAD + t] = logf(fmaxf(p, 1e-8f));
    }
}

// ---------------- cep: DCT, thread = (frame, coeff). 136 blocks x 320 thr ----------------
__global__ void __launch_bounds__(320) k_cep() {
    __shared__ float lps[NB * 16];            // [n][t], 6 KB
    __shared__ float dctt[NC * NB];           // [c][n], 7.5 KB
    const int tid = threadIdx.x;
    const int t0 = blockIdx.x * 16;

    for (int idx = tid; idx < NB * 4; idx += 320) {
        int n = idx >> 2, p = idx & 3;
        float4 v = *(const float4*)(g_lpT + (size_t)n * TPAD + t0 + p * 4);
        *(float4*)(lps + n * 16 + p * 4) = v;
    }
    for (int idx = tid; idx < NC * NB; idx += 320) dctt[idx] = g_dct[idx];
    __syncthreads();

    const int tl = tid & 15;
    const int c  = tid >> 4;                  // 0..19
    float acc = 0.0f;
    #pragma unroll 8
    for (int n = 0; n < NB; n++)
        acc = fmaf(lps[n * 16 + tl], dctt[c * NB + n], acc);
    g_c[c * TPAD + t0 + tl] = acc;            // padding t ok (unused)
}

// ---------------- fused normalize + delta + delta-delta ----------------
__global__ void __launch_bounds__(256) k_tail(float* __restrict__ out) {
    const int c = blockIdx.x;       // 0..19
    const int tid = threadIdx.x;
    __shared__ float cn[T_FRAMES];
    __shared__ float d1s[T_FRAMES];
    __shared__ float red[256];

    float s = 0.0f;
    for (int t = tid; t < T_FRAMES; t += 256) {
        float v = g_c[c * TPAD + t];
        cn[t] = v;
        s += v;
    }
    red[tid] = s; __syncthreads();
    for (int o = 128; o; o >>= 1) { if (tid < o) red[tid] += red[tid + o]; __syncthreads(); }
    float mean = red[0] / (float)T_FRAMES;
    __syncthreads();
    float ss = 0.0f;
    for (int t = tid; t < T_FRAMES; t += 256) { float d = cn[t] - mean; ss += d * d; }
    red[tid] = ss; __syncthreads();
    for (int o = 128; o; o >>= 1) { if (tid < o) red[tid] += red[tid + o]; __syncthreads(); }
    float inv = 1.0f / (sqrtf(red[0] / (float)(T_FRAMES - 1)) + 1e-8f);
    __syncthreads();
    for (int t = tid; t < T_FRAMES; t += 256) cn[t] = (cn[t] - mean) * inv;
    __syncthreads();

    for (int t = tid; t < T_FRAMES; t += 256) {
        int tp1 = min(t + 1, T_FRAMES - 1), tm1 = max(t - 1, 0);
        int tp2 = min(t + 2, T_FRAMES - 1), tm2 = max(t - 2, 0);
        float d = ((cn[tp1] - cn[tm1]) + 2.0f * (cn[tp2] - cn[tm2])) * 0.1f;
        d1s[t] = d;
        out[t * 60 + c]      = cn[t];
        out[t * 60 + 20 + c] = d;
    }
    __syncthreads();
    for (int t = tid; t < T_FRAMES; t += 256) {
        int tp1 = min(t + 1, T_FRAMES - 1), tm1 = max(t - 1, 0);
        int tp2 = min(t + 2, T_FRAMES - 1), tm2 = max(t - 2, 0);
        float d = ((d1s[tp1] - d1s[tm1]) + 2.0f * (d1s[tp2] - d1s[tm2])) * 0.1f;
        out[t * 60 + 40 + c] = d;
    }
}

// ---------------- launch ----------------
extern "C" void kernel_launch(void* const* d_in, const int* in_sizes, int n_in,
                              void* d_out, int out_size) {
    const float* wav = (const float*)d_in[0];
    float* out = (float*)d_out;

    const int s1_smem = (16384 + 128 * 64) * 4;   // 98304
    const int s2_smem = (FTILE2 * GS_STR + FTILE2 * HS_STR + 9 * MP_STR
                         + W2ROWS * FTILE2) * 8;  // 80712
    cudaFuncSetAttribute(k_s1, cudaFuncAttributeMaxDynamicSharedMemorySize, s1_smem);
    cudaFuncSetAttribute(k_s2, cudaFuncAttributeMaxDynamicSharedMemorySize, s2_smem);

    k_setup<<<SETUP_BLKS, 256>>>(wav);
    k_s1<<<dim3(18, 18), 256, s1_smem>>>();
    k_s2<<<dim3(FB2, TT2), 256, s2_smem>>>();
    k_cep<<<TPAD / 16, 320>>>();
    k_tail<<<NC, 256>>>(out);
}

// round 14
// speedup vs baseline: 1.5403x; 1.0881x over previous
#include <cuda_runtime.h>
#include <cstdint>

// ---------------- constants ----------------
#define T_FRAMES 2049
#define NWAV     262144
#define MW       16699
#define LEFT     24418
#define PADR     32768
#define NB       96
#define NC       20
#define EC2      1152           // [full 576 | partial 576] moment cols
#define GROWS    2368
#define XW_LEN   294912         // 2304*128
#define TPAD     2176

// stage-2 tiling: 18 complex freqs x 120 frames, 288 threads
#define FTILE2   18
#define TTILE2   120
#define TT2      18
#define FB2      32
#define THR2     288
#define GS_STR   253            // float2 stride, rows 0..251
#define HS_STR   241            // rows 0..239
#define MP_STR   121            // rows 0..119
#define ZS_STR   121
#define W2ROWS   24

// setup kernel block ranges
#define PAD_BLKS 1152
#define E_BLKS   48             // 96 pairs x 128 r / 256
#define NF       576
#define W_ELEMS  (NF * W2ROWS)
#define W_BLKS   54
#define SETUP_BLKS (PAD_BLKS + E_BLKS + W_BLKS + 1)

// ---------------- device scratch ----------------
__device__ float g_xw[XW_LEN];
__device__ float g_e[128 * EC2];
__device__ float g_w2[W2ROWS * 1152];
__device__ float g_g[(size_t)GROWS * EC2];
__device__ float g_lpT[(size_t)NB * TPAD];      // log cqt power, [bin][t]
__device__ float g_c[NC * TPAD];                // cepstra, [c][t]
__device__ float g_alpha[NB];
__device__ float g_dct[NC * NB];

// ---------------- f32x2 helpers ----------------
__device__ __forceinline__ void fma2(unsigned long long& acc,
                                     unsigned long long a, unsigned long long b) {
    asm("fma.rn.f32x2 %0, %1, %2, %0;" : "+l"(acc) : "l"(a), "l"(b));
}
__device__ __forceinline__ unsigned long long dup2(float x) {
    unsigned long long r;
    asm("mov.b64 %0, {%1, %1};" : "=l"(r) : "f"(x));
    return r;
}
__device__ __forceinline__ unsigned long long pk2(float x, float y) {
    unsigned long long r;
    asm("mov.b64 %0, {%1, %2};" : "=l"(r) : "f"(x), "f"(y));
    return r;
}
__device__ __forceinline__ float2 upk2(unsigned long long v) {
    float2 r;
    asm("mov.b64 {%0, %1}, %2;" : "=f"(r.x), "=f"(r.y) : "l"(v));
    return r;
}

// ---------------- inline bin computation ----------------
__device__ __forceinline__ int bin_of(int bi) {   // bi 0..191
    int i = bi >> 1;
    float cq   = 32.7f * exp2f((float)i / 24.0f);
    float idxf = cq / 8000.0f * 32768.0f;
    int lo = (int)idxf;
    lo = max(0, min(lo, 32767));
    return lo + (bi & 1);
}

// rho offset for local freq index fi (0..17 within block)
__device__ __forceinline__ float rho_of(int fi) {
    int bl = fi / 3, j = fi - 3 * bl;
    int h = bl & 1;
    float sgn = (j == 1) ? -1.0f : (j == 2) ? 1.0f : 0.0f;
    return 6.283185307f * ((h ? 0.5f : -0.5f) * (1.0f / 65536.0f) + sgn * (1.0f / (float)MW));
}

// ---------------- fused setup ----------------
__global__ void __launch_bounds__(256) k_setup(const float* __restrict__ wav) {
    const int blk = blockIdx.x;
    const int tid = threadIdx.x;

    if (blk < PAD_BLKS) {
        int i = blk * 256 + tid;
        int q = i + (LEFT - PADR);
        int idx = (q < 0) ? -q : ((q >= NWAV) ? (2 * NWAV - 2 - q) : q);
        idx = max(0, min(idx, NWAV - 1));
        g_xw[i] = wav[idx];
        return;
    }
    if (blk < PAD_BLKS + E_BLKS) {
        // one sincospif per (pair, r); moments derived by r, r^2 scaling
        int lin = (blk - PAD_BLKS) * 256 + tid;     // 0..12287
        int p = lin % 96, r = lin / 96;
        int b = bin_of(2 * p);                      // lo bin of pair
        int mod = ((2 * b + 1) * r) & 131071;
        float x = (float)mod * (1.0f / 65536.0f);
        if (x >= 1.0f) x -= 2.0f;
        float s, c;
        sincospif(x, &s, &c);
        float re = c, im = -s;
        float rf = (float)r;
        float* e = g_e + r * EC2 + p * 6;
        e[0] = re;            e[1] = im;
        e[2] = rf * re;       e[3] = rf * im;
        e[4] = rf * rf * re;  e[5] = rf * rf * im;
        float zp = (r < 59) ? 1.0f : 0.0f;
        e[576]     = zp * re;            e[577]     = zp * im;
        e[578]     = zp * rf * re;       e[579]     = zp * rf * im;
        e[580]     = zp * rf * rf * re;  e[581]     = zp * rf * rf * im;
        return;
    }
    if (blk < PAD_BLKS + E_BLKS + W_BLKS) {
        int lin = (blk - PAD_BLKS - E_BLKS) * 256 + tid;
        if (lin >= W_ELEMS) return;
        int fi = lin / W2ROWS;
        int u  = lin % W2ROWS;
        int bi = fi / 3, j = fi % 3;
        int b  = bin_of(bi);
        int sgn = (j == 1) ? -1 : (j == 2) ? 1 : 0;
        float wre, wim;
        if (u < 13) {
            float fa = (float)((b * u) & 511) * (1.0f / 512.0f);
            float fbv = (float)(128 * u) * (1.0f / (float)MW);
            float fr = fa + (float)sgn * fbv;
            float s, c;
            sincospif(2.0f * fr, &s, &c);
            wre = c; wim = -s;
        } else {
            float coeff = (j == 0) ? 0.5f : -0.25f;
            int e = (u < 23) ? 13 * (u - 13) : 130;
            float fa = (float)((b * e) & 511) * (1.0f / 512.0f);
            float fbv = (float)((128 * e) % MW) * (1.0f / (float)MW);
            float fr = fa + (float)sgn * fbv;
            float s, c;
            sincospif(2.0f * fr, &s, &c);
            wre = coeff * c;
            wim = -coeff * s;
        }
        g_w2[u * 1152 + 2 * fi]     = wre;
        g_w2[u * 1152 + 2 * fi + 1] = wim;
        return;
    }
    // last block: alpha + dct
    if (tid < NB) {
        float cq   = 32.7f * exp2f((float)tid / 24.0f);
        float idxf = cq / 8000.0f * 32768.0f;
        int lo = (int)idxf;
        lo = max(0, min(lo, 32767));
        g_alpha[tid] = idxf - (float)lo;
    }
    for (int idx = tid; idx < NC * NB; idx += 256) {
        int c = idx / NB, n = idx % NB;
        g_dct[idx] = cospif((float)(c * (2 * n + 1)) / 192.0f);
    }
}

// ---------------- stage 1: moment GEMM, block 128 rows x 64 cols ----------------
__global__ void __launch_bounds__(256) k_s1() {
    extern __shared__ float smem[];
    float* xs = smem;            // 16384 floats
    float* ts = smem + 16384;    // up to 128 x 64

    const int bx = blockIdx.x;                 // 0..17
    const int c0 = (bx < 9) ? bx * 64 : 576 + (bx - 9) * 64;
    const int K  = (bx < 9) ? 128 : 64;
    const int s0 = blockIdx.y * 128;
    const int tid = threadIdx.x;
    const int cg = tid & 15;
    const int fg = tid >> 4;

    const float4* xsrc = (const float4*)(g_xw + s0 * 128);
    #pragma unroll
    for (int i = tid; i < 4096; i += 256)
        ((float4*)xs)[i] = xsrc[i];
    for (int i = tid; i < K * 16; i += 256) {
        int kk = i >> 4, c4 = i & 15;
        ((float4*)ts)[i] = *(const float4*)(g_e + kk * EC2 + c0 + c4 * 4);
    }
    __syncthreads();

    unsigned long long acc[8][2] = {};
    for (int kk0 = 0; kk0 < K; kk0 += 4) {
        float4 af[8];
        #pragma unroll
        for (int r = 0; r < 8; r++)
            af[r] = *(const float4*)(xs + (fg * 8 + r) * 128 + kk0);
        #pragma unroll
        for (int k = 0; k < 4; k++) {
            ulonglong2 bb = *(const ulonglong2*)(ts + (kk0 + k) * 64 + cg * 4);
            #pragma unroll
            for (int r = 0; r < 8; r++) {
                unsigned long long ad = dup2(((const float*)&af[r])[k]);
                fma2(acc[r][0], ad, bb.x);
                fma2(acc[r][1], ad, bb.y);
            }
        }
    }

    #pragma unroll
    for (int r = 0; r < 8; r++) {
        int s = s0 + fg * 8 + r;
        ulonglong2 v;
        v.x = acc[r][0]; v.y = acc[r][1];
        *(ulonglong2*)(g_g + (size_t)s * EC2 + c0 + cg * 4) = v;
    }
}

// ---------------- stage 2: moment expand + two-level FIR + fused power/log ----------------
__global__ void __launch_bounds__(THR2) k_s2() {
    extern __shared__ float smem[];
    float2* Gs = (float2*)smem;               // [18][GS_STR], rows 0..251
    float2* Hs = Gs + FTILE2 * GS_STR;        // [18][HS_STR], rows 0..239; alias Ms[9][GS_STR]
    float2* Mp = Hs + FTILE2 * HS_STR;        // [9][MP_STR], rows 0..119
    float2* Wt = Mp + 9 * MP_STR;             // [24][18]

    const int m   = blockIdx.x;               // bin-triple 0..31
    const int t0  = blockIdx.y * TTILE2;
    const int tid = threadIdx.x;
    float2* Ms = Hs;                          // alias while loading

    for (int idx = tid; idx < 252 * 9; idx += THR2) {
        int row = idx / 9, q = idx % 9;
        Ms[q * GS_STR + row] = *(const float2*)(g_g + (size_t)(t0 + row) * EC2 + 18 * m + 2 * q);
    }
    for (int idx = tid; idx < 120 * 9; idx += THR2) {
        int row = idx / 9, q = idx % 9;
        Mp[q * MP_STR + row] = *(const float2*)(g_g + (size_t)(t0 + 130 + row) * EC2 + 576 + 18 * m + 2 * q);
    }
    for (int idx = tid; idx < W2ROWS * 9; idx += THR2) {
        int u = idx / 9, p = idx % 9;
        float4 v = *(const float4*)(g_w2 + u * 1152 + m * FTILE2 * 2 + p * 4);
        Wt[u * FTILE2 + 2 * p]     = make_float2(v.x, v.y);
        Wt[u * FTILE2 + 2 * p + 1] = make_float2(v.z, v.w);
    }
    __syncthreads();

    // ---- expand moments -> Gs (2nd-order Taylor), rows 0..251 ----
    for (int idx = tid; idx < 252 * 18; idx += THR2) {
        int fi = idx % 18, row = idx / 18;
        int pp = (fi / 3) >> 1;
        float rho = rho_of(fi);
        float r2 = 0.5f * rho * rho;
        float2 m0 = Ms[(pp * 3 + 0) * GS_STR + row];
        float2 m1 = Ms[(pp * 3 + 1) * GS_STR + row];
        float2 m2 = Ms[(pp * 3 + 2) * GS_STR + row];
        float2 g;
        g.x = m0.x + rho * m1.y - r2 * m2.x;
        g.y = m0.y - rho * m1.x - r2 * m2.y;
        Gs[fi * GS_STR + row] = g;
    }
    __syncthreads();

    // ---- H phase: H[tau,f] = sum_{w<13} rho^w G[tau+w,f], rows 0..239 ----
    for (int cid = tid; cid < 540; cid += THR2) {    // 18 f x 30 chunks of 8 rows
        int f = cid % 18, ch = cid / 18;
        int base = ch * 8;
        const float2* gb = Gs + f * GS_STR + base;
        unsigned long long gw[8], gsw[8], acc[8];
        #pragma unroll
        for (int r = 0; r < 8; r++) acc[r] = 0ULL;
        #pragma unroll
        for (int i = 0; i < 7; i++) {
            float2 g = gb[i];
            gw[i]  = pk2(g.x, g.y);
            gsw[i] = pk2(-g.y, g.x);
        }
        #pragma unroll
        for (int u = 0; u < 13; u++) {
            float2 g = gb[u + 7];
            gw[(u + 7) & 7]  = pk2(g.x, g.y);
            gsw[(u + 7) & 7] = pk2(-g.y, g.x);
            float2 wt = Wt[u * FTILE2 + f];
            unsigned long long wx = dup2(wt.x);
            unsigned long long wy = dup2(wt.y);
            #pragma unroll
            for (int r = 0; r < 8; r++) {
                fma2(acc[r], wx, gw[(u + r) & 7]);
                fma2(acc[r], wy, gsw[(u + r) & 7]);
            }
        }
        float2* hb = Hs + f * HS_STR + base;
        #pragma unroll
        for (int r = 0; r < 8; r++) hb[r] = upk2(acc[r]);
    }
    __syncthreads();

    // ---- Z phase: 10 coarse taps on H + 3 partial taps on Mp ----
    const int f  = tid % 18;
    const int tg = tid / 18;                   // 0..14 valid
    const bool active = (tid < 270);
    const int base = tg * 8;
    unsigned long long acc[8] = {};
    if (active) {
        const float2* hb = Hs + f * HS_STR + base;
        #pragma unroll
        for (int v = 0; v < 10; v++) {
            float2 wt = Wt[(13 + v) * FTILE2 + f];
            unsigned long long wx = dup2(wt.x);
            unsigned long long wy = dup2(wt.y);
            #pragma unroll
            for (int r = 0; r < 8; r++) {
                float2 h = hb[13 * v + r];
                fma2(acc[r], wx, pk2(h.x, h.y));
                fma2(acc[r], wy, pk2(-h.y, h.x));
            }
        }
        float2 wt = Wt[23 * FTILE2 + f];
        float rho = rho_of(f);
        float r2 = 0.5f * rho * rho;
        float2 W[3];
        W[0] = wt;
        W[1] = make_float2(rho * wt.y, -rho * wt.x);
        W[2] = make_float2(-r2 * wt.x, -r2 * wt.y);
        int pp = (f / 3) >> 1;
        #pragma unroll
        for (int mm = 0; mm < 3; mm++) {
            unsigned long long wx = dup2(W[mm].x);
            unsigned long long wy = dup2(W[mm].y);
            const float2* gp = Mp + (pp * 3 + mm) * MP_STR + base;
            #pragma unroll
            for (int r = 0; r < 8; r++) {
                float2 g = gp[r];
                fma2(acc[r], wx, pk2(g.x, g.y));
                fma2(acc[r], wy, pk2(-g.y, g.x));
            }
        }
    }
    __syncthreads();
    float2* Zs = Gs;
    if (active) {
        #pragma unroll
        for (int r = 0; r < 8; r++)
            Zs[f * ZS_STR + base + r] = upk2(acc[r]);
    }
    __syncthreads();

    // ---- combine triples -> power -> lerp -> log ----
    for (int idx = tid; idx < 3 * TTILE2; idx += THR2) {
        int q  = idx / TTILE2;
        int tl = idx % TTILE2;
        int t  = t0 + tl;
        if (t >= T_FRAMES) continue;
        const float2* zq = Zs + (6 * q) * ZS_STR + tl;
        float2 z0 = zq[0];
        float2 z1 = zq[ZS_STR];
        float2 z2 = zq[2 * ZS_STR];
        float2 z3 = zq[3 * ZS_STR];
        float2 z4 = zq[4 * ZS_STR];
        float2 z5 = zq[5 * ZS_STR];
        float lre = z0.x + z1.x + z2.x, lim = z0.y + z1.y + z2.y;
        float hre = z3.x + z4.x + z5.x, him = z3.y + z4.y + z5.y;
        float plo = lre * lre + lim * lim;
        float phi = hre * hre + him * him;
        int bin = 3 * m + q;
        float al = g_alpha[bin];
        float p = (1.0f - al) * plo + al * phi;
        g_lpT[(size_t)bin * TPAD + t] = logf(fmaxf(p, 1e-8f));
    }
}

// ---------------- cep: DCT, thread = (frame, coeff), 4 accumulators ----------------
__global__ void __launch_bounds__(320) k_cep() {
    __shared__ float lps[NB * 16];            // [n][t], 6 KB
    __shared__ float dctt[NC * NB];           // [c][n], 7.5 KB
    const int tid = threadIdx.x;
    const int t0 = blockIdx.x * 16;

    for (int idx = tid; idx < NB * 4; idx += 320) {
        int n = idx >> 2, p = idx & 3;
        float4 v = *(const float4*)(g_lpT + (size_t)n * TPAD + t0 + p * 4);
        *(float4*)(lps + n * 16 + p * 4) = v;
    }
    for (int idx = tid; idx < NC * NB; idx += 320) dctt[idx] = g_dct[idx];
    __syncthreads();

    const int tl = tid & 15;
    const int c  = tid >> 4;                  // 0..19
    float a0 = 0.0f, a1 = 0.0f, a2 = 0.0f, a3 = 0.0f;
    #pragma unroll 4
    for (int n = 0; n < 24; n++) {
        a0 = fmaf(lps[n * 16 + tl],        dctt[c * NB + n],      a0);
        a1 = fmaf(lps[(n + 24) * 16 + tl], dctt[c * NB + n + 24], a1);
        a2 = fmaf(lps[(n + 48) * 16 + tl], dctt[c * NB + n + 48], a2);
        a3 = fmaf(lps[(n + 72) * 16 + tl], dctt[c * NB + n + 72], a3);
    }
    g_c[c * TPAD + t0 + tl] = (a0 + a1) + (a2 + a3);
}

// ---------------- fused normalize + delta + delta-delta ----------------
__global__ void __launch_bounds__(256) k_tail(float* __restrict__ out) {
    const int c = blockIdx.x;       // 0..19
    const int tid = threadIdx.x;
    __shared__ float cn[T_FRAMES];
    __shared__ float d1s[T_FRAMES];
    __shared__ float red[256];

    float s = 0.0f;
    for (int t = tid; t < T_FRAMES; t += 256) {
        float v = g_c[c * TPAD + t];
        cn[t] = v;
        s += v;
    }
    red[tid] = s; __syncthreads();
    for (int o = 128; o; o >>= 1) { if (tid < o) red[tid] += red[tid + o]; __syncthreads(); }
    float mean = red[0] / (float)T_FRAMES;
    __syncthreads();
    float ss = 0.0f;
    for (int t = tid; t < T_FRAMES; t += 256) { float d = cn[t] - mean; ss += d * d; }
    red[tid] = ss; __syncthreads();
    for (int o = 128; o; o >>= 1) { if (tid < o) red[tid] += red[tid + o]; __syncthreads(); }
    float inv = 1.0f / (sqrtf(red[0] / (float)(T_FRAMES - 1)) + 1e-8f);
    __syncthreads();
    for (int t = tid; t < T_FRAMES; t += 256) cn[t] = (cn[t] - mean) * inv;
    __syncthreads();

    for (int t = tid; t < T_FRAMES; t += 256) {
        int tp1 = min(t + 1, T_FRAMES - 1), tm1 = max(t - 1, 0);
        int tp2 = min(t + 2, T_FRAMES - 1), tm2 = max(t - 2, 0);
        float d = ((cn[tp1] - cn[tm1]) + 2.0f * (cn[tp2] - cn[tm2])) * 0.1f;
        d1s[t] = d;
        out[t * 60 + c]      = cn[t];
        out[t * 60 + 20 + c] = d;
    }
    __syncthreads();
    for (int t = tid; t < T_FRAMES; t += 256) {
        int tp1 = min(t + 1, T_FRAMES - 1), tm1 = max(t - 1, 0);
        int tp2 = min(t + 2, T_FRAMES - 1), tm2 = max(t - 2, 0);
        float d = ((d1s[tp1] - d1s[tm1]) + 2.0f * (d1s[tp2] - d1s[tm2])) * 0.1f;
        out[t * 60 + 40 + c] = d;
    }
}

// ---------------- launch ----------------
extern "C" void kernel_launch(void* const* d_in, const int* in_sizes, int n_in,
                              void* d_out, int out_size) {
    const float* wav = (const float*)d_in[0];
    float* out = (float*)d_out;

    const int s1_smem = (16384 + 128 * 64) * 4;   // 98304
    const int s2_smem = (FTILE2 * GS_STR + FTILE2 * HS_STR + 9 * MP_STR
                         + W2ROWS * FTILE2) * 8;  // 83016
    cudaFuncSetAttribute(k_s1, cudaFuncAttributeMaxDynamicSharedMemorySize, s1_smem);
    cudaFuncSetAttribute(k_s2, cudaFuncAttributeMaxDynamicSharedMemorySize, s2_smem);

    k_setup<<<SETUP_BLKS, 256>>>(wav);
    k_s1<<<dim3(18, 18), 256, s1_smem>>>();
    k_s2<<<dim3(FB2, TT2), THR2, s2_smem>>>();
    k_cep<<<TPAD / 16, 320>>>();
    k_tail<<<NC, 256>>>(out);
}